// round 12
// baseline (speedup 1.0000x reference)
#include <cuda_runtime.h>
#include <cuda_bf16.h>
#include <cstdint>

#define BB 16
#define SS 2048
#define DD 64
#define TQ 128
#define NJ 128
#define NT 384
#define NCW 8              // compute warps; warps 8-11 are producers
#define NTILES (SS / NJ)

// smem layout (from 1024-aligned base)
#define OQH 0
#define OQL 16384
#define OKV0 32768         // buffer 0: Kh,Kl,Vh,Vl (16KB each)
#define OKV1 98304         // buffer 1
#define OINV 163840        // 128 floats of 1/rowsum
#define SMEM_DYN (163840 + 512 + 1024)

#define SWZ(o) ((o) ^ (((o) >> 3) & 0x70u))

static __device__ __forceinline__ uint32_t packbf(float lo, float hi) {
    uint32_t r;
    asm("cvt.rn.bf16x2.f32 %0, %1, %2;" : "=r"(r) : "f"(hi), "f"(lo));
    return r;
}
static __device__ __forceinline__ float ubf(uint32_t u) { return __uint_as_float(u); }

static __device__ __forceinline__ void ldsm4(uint32_t* r, uint32_t a) {
    asm volatile("ldmatrix.sync.aligned.m8n8.x4.shared.b16 {%0,%1,%2,%3}, [%4];"
        : "=r"(r[0]), "=r"(r[1]), "=r"(r[2]), "=r"(r[3]) : "r"(a));
}
static __device__ __forceinline__ void ldsm4t(uint32_t* r, uint32_t a) {
    asm volatile("ldmatrix.sync.aligned.m8n8.x4.trans.shared.b16 {%0,%1,%2,%3}, [%4];"
        : "=r"(r[0]), "=r"(r[1]), "=r"(r[2]), "=r"(r[3]) : "r"(a));
}
static __device__ __forceinline__ void mma16816(float* c, const uint32_t* a,
                                                uint32_t b0, uint32_t b1) {
    asm volatile("mma.sync.aligned.m16n8k16.row.col.f32.bf16.bf16.f32 "
        "{%0,%1,%2,%3}, {%4,%5,%6,%7}, {%8,%9}, {%0,%1,%2,%3};"
        : "+f"(c[0]), "+f"(c[1]), "+f"(c[2]), "+f"(c[3])
        : "r"(a[0]), "r"(a[1]), "r"(a[2]), "r"(a[3]), "r"(b0), "r"(b1));
}
static __device__ __forceinline__ uint32_t s2u(const void* p) {
    uint32_t a;
    asm("{ .reg .u64 t; cvta.to.shared.u64 t, %1; cvt.u32.u64 %0, t; }" : "=r"(a) : "l"(p));
    return a;
}
static __device__ __forceinline__ uint32_t b2b(uint32_t wv, int sh) {
    uint32_t r = 0;
    r |= ((wv & 0x000000FFu) ? 1u : 0u) << sh;
    r |= ((wv & 0x0000FF00u) ? 1u : 0u) << (sh + 1);
    r |= ((wv & 0x00FF0000u) ? 1u : 0u) << (sh + 2);
    r |= ((wv & 0xFF000000u) ? 1u : 0u) << (sh + 3);
    return r;
}

// convert 8 fp32 -> bf16 hi/lo packed pairs, store swizzled
static __device__ __forceinline__ void cvt_store8(const float* y, char* sh, char* sl,
                                                  int row, int c8)
{
    uint32_t h[4], l[4];
#pragma unroll
    for (int p = 0; p < 4; p++) {
        h[p] = packbf(y[2*p], y[2*p+1]);
        float f0 = ubf(h[p] << 16), f1 = ubf(h[p] & 0xFFFF0000u);
        l[p] = packbf(y[2*p] - f0, y[2*p+1] - f1);
    }
    uint32_t off = SWZ((uint32_t)(row * 128 + c8 * 2));
    *(uint4*)(sh + off) = make_uint4(h[0], h[1], h[2], h[3]);
    *(uint4*)(sl + off) = make_uint4(l[0], l[1], l[2], l[3]);
}

// stage a [128 x 64] fp32 tile as bf16 hi/lo (flexible thread set)
static __device__ __forceinline__ void stage_bf(const float* __restrict__ g,
                                                char* sh, char* sl, float sc,
                                                int t0, int step)
{
    for (int i = t0; i < 1024; i += step) {
        int row = i >> 3, c8 = (i & 7) << 3;
        float4 a = *(const float4*)(g + row * 64 + c8);
        float4 b = *(const float4*)(g + row * 64 + c8 + 4);
        float y[8] = {a.x*sc, a.y*sc, a.z*sc, a.w*sc, b.x*sc, b.y*sc, b.z*sc, b.w*sc};
        cvt_store8(y, sh, sl, row, c8);
    }
}

// stage K and V tiles into a KV buffer (flexible thread set)
static __device__ __forceinline__ void stage_kv(const float* __restrict__ kg,
                                                const float* __restrict__ vg,
                                                char* buf, int t0, int step)
{
    for (int i = t0; i < 2048; i += step) {
        int ii = i & 1023;
        const float* src = (i < 1024) ? kg : vg;
        char* sh = buf + ((i < 1024) ? 0 : 32768);
        char* sl = sh + 16384;
        int row = ii >> 3, c8 = (ii & 7) << 3;
        float4 a = *(const float4*)(src + row * 64 + c8);
        float4 b = *(const float4*)(src + row * 64 + c8 + 4);
        float y[8] = {a.x, a.y, a.z, a.w, b.x, b.y, b.z, b.w};
        cvt_store8(y, sh, sl, row, c8);
    }
}

__global__ __launch_bounds__(NT) void sdpa_ws_kernel(
    const float* __restrict__ q, const float* __restrict__ k,
    const float* __restrict__ v, const void* __restrict__ maskp,
    float* __restrict__ out, float* __restrict__ attn)
{
    const int b   = blockIdx.y;
    const int q0  = blockIdx.x * TQ;
    const int tid = threadIdx.x;
    const int w   = tid >> 5;
    const int lid = tid & 31;
    const int g   = lid >> 2;
    const int t2  = lid & 3;
    const int bq  = b * SS + q0;

    extern __shared__ char dsm_raw[];
    char* dsm = (char*)(((uintptr_t)dsm_raw + 1023) & ~(uintptr_t)1023);
    float* sInv = (float*)(dsm + OINV);
    const uint32_t uQH = s2u(dsm + OQH), uQL = s2u(dsm + OQL);
    const uint32_t uB0 = s2u(dsm + OKV0), uB1 = s2u(dsm + OKV1);

    const float* qb = q + ((size_t)bq) * DD;
    const float* kb = k + (size_t)b * SS * DD;
    const float* vb = v + (size_t)b * SS * DD;
    const unsigned char* m8b  = (const unsigned char*)maskp + (size_t)b * SS * SS;
    const uint32_t*      m32b = (const uint32_t*)maskp + (size_t)b * SS * SS;

    // ---- fused mask-dtype detect over this CTA's own slice ----
    int pF = 0, pB = 0;
    {
        uint4 u = __ldcs((const uint4*)(m32b + (size_t)q0 * SS) + tid);
        uint32_t ws[4] = {u.x, u.y, u.z, u.w};
#pragma unroll
        for (int i = 0; i < 4; i++) {
            if (ws[i] == 0x3F800000u) pF = 1;
            else if (ws[i] > 1u)      pB = 1;
        }
    }

    // prologue staging by all threads: Q (scaled) + KV tile0 into buf0
    stage_bf(qb, dsm + OQH, dsm + OQL, 0.125f, tid, NT);
    stage_kv(kb, vb, dsm + OKV0, tid, NT);

    const int anyF = __syncthreads_or(pF);
    const int anyB = __syncthreads_or(pB);
    const int mk = anyF ? 2 : (anyB ? 0 : 1);   // 0=uint8, 1=int32, 2=float32

    // ldmatrix lane address patterns
    const int krow = (lid & 7) + ((lid >> 4) & 1) * 8;
    const int kbyt = ((lid >> 3) & 1) * 16;
    const int qrow = (lid & 7) + ((lid >> 3) & 1) * 8;
    const int qbyt = ((lid >> 4) & 1) * 16;

    float OD[8][4];
#pragma unroll
    for (int i = 0; i < 8; i++)
#pragma unroll
        for (int jx = 0; jx < 4; jx++) OD[i][jx] = 0.f;

    float rs0 = 0.f, rs1 = 0.f;

    for (int t = 0; t < NTILES; t++) {
        const int j0 = t * NJ;
        if (t > 0) __syncthreads();   // buf[t&1] produced; buf[(t+1)&1] free

        if (w >= NCW) {
            // -------- producer warps: stage next tile into the idle buffer --------
            if (t + 1 < NTILES)
                stage_kv(kb + (size_t)(j0 + NJ) * DD, vb + (size_t)(j0 + NJ) * DD,
                         dsm + ((t & 1) ? OKV0 : OKV1), tid - NCW * 32, NT - NCW * 32);
            continue;
        }

        // -------- compute warps --------
        const uint32_t uKB = (t & 1) ? uB1 : uB0;
        const uint32_t uKH = uKB, uKL = uKB + 16384;
        const uint32_t uVH = uKB + 32768, uVL = uKB + 49152;

        // hoisted mask loads (consumed after GEMM1 half 0)
        uint4 mr0[8], mr1[8];
        const size_t mrow0 = (size_t)(q0 + w * 16 + g) * SS + j0 + t2 * 32;
        if (mk == 0) {
            const uint4* p0 = (const uint4*)(m8b + mrow0);
            const uint4* p1 = (const uint4*)(m8b + mrow0 + (size_t)8 * SS);
            mr0[0] = __ldcs(p0);  mr0[1] = __ldcs(p0 + 1);
            mr1[0] = __ldcs(p1);  mr1[1] = __ldcs(p1 + 1);
        } else {
            const uint4* p0 = (const uint4*)(m32b + mrow0);
            const uint4* p1 = (const uint4*)(m32b + mrow0 + (size_t)8 * SS);
#pragma unroll
            for (int ii = 0; ii < 8; ii++) { mr0[ii] = __ldcs(p0 + ii); mr1[ii] = __ldcs(p1 + ii); }
        }

        float* ar0 = attn + ((size_t)(bq + w * 16 + g)) * SS + j0;
        float* ar1 = ar0 + (size_t)8 * SS;
        uint32_t mw0[4], mw1[4];

#pragma unroll
        for (int hf = 0; hf < 2; hf++) {
            float C[8][4];
#pragma unroll
            for (int fn = 0; fn < 8; fn++)
#pragma unroll
                for (int jx = 0; jx < 4; jx++) C[fn][jx] = 0.f;

#pragma unroll
            for (int ks = 0; ks < 4; ks++) {
                uint32_t qh[4], ql[4];
                uint32_t qoff = (uint32_t)(w * 2048 +
                    (((qrow * 128) | (ks * 32) | qbyt) ^ ((qrow & 7) << 4)));
                ldsm4(qh, uQH + qoff);
                ldsm4(ql, uQL + qoff);
#pragma unroll
                for (int jj = 0; jj < 4; jj++) {
                    const int jg = hf * 4 + jj;
                    uint32_t kh[4], kl[4];
                    uint32_t koff = (uint32_t)(jg * 2048 +
                        (((krow * 128) | (ks * 32) | kbyt) ^ ((krow & 7) << 4)));
                    ldsm4(kh, uKH + koff);
                    ldsm4(kl, uKL + koff);
                    mma16816(C[2*jj],   qh, kh[0], kh[1]);
                    mma16816(C[2*jj+1], qh, kh[2], kh[3]);
                    mma16816(C[2*jj],   qh, kl[0], kl[1]);
                    mma16816(C[2*jj+1], qh, kl[2], kl[3]);
                    mma16816(C[2*jj],   ql, kh[0], kh[1]);
                    mma16816(C[2*jj+1], ql, kh[2], kh[3]);
                }
            }

            if (hf == 0) {
                // pack hoisted mask words (loads now long complete)
                uint32_t myb0, myb1;
                if (mk == 0) {
                    myb0 = b2b(mr0[0].x,0)|b2b(mr0[0].y,4)|b2b(mr0[0].z,8)|b2b(mr0[0].w,12)
                         | b2b(mr0[1].x,16)|b2b(mr0[1].y,20)|b2b(mr0[1].z,24)|b2b(mr0[1].w,28);
                    myb1 = b2b(mr1[0].x,0)|b2b(mr1[0].y,4)|b2b(mr1[0].z,8)|b2b(mr1[0].w,12)
                         | b2b(mr1[1].x,16)|b2b(mr1[1].y,20)|b2b(mr1[1].z,24)|b2b(mr1[1].w,28);
                } else {
                    myb0 = 0; myb1 = 0;
#pragma unroll
                    for (int ii = 0; ii < 8; ii++) {
                        uint4 a = mr0[ii];
                        myb0 |= (a.x?1u:0u)<<(ii*4)   | (a.y?1u:0u)<<(ii*4+1)
                              | (a.z?1u:0u)<<(ii*4+2) | (a.w?1u:0u)<<(ii*4+3);
                        uint4 c = mr1[ii];
                        myb1 |= (c.x?1u:0u)<<(ii*4)   | (c.y?1u:0u)<<(ii*4+1)
                              | (c.z?1u:0u)<<(ii*4+2) | (c.w?1u:0u)<<(ii*4+3);
                    }
                }
#pragma unroll
                for (int i = 0; i < 4; i++) {
                    mw0[i] = __shfl_sync(0xffffffffu, myb0, (lid & ~3) | i);
                    mw1[i] = __shfl_sync(0xffffffffu, myb1, (lid & ~3) | i);
                }
            }

            // per-slab epilogue + GEMM2
#pragma unroll
            for (int jj = 0; jj < 4; jj++) {
                const int jg = hf * 4 + jj;
                uint32_t phi[4], plo[4];
#pragma unroll
                for (int fo = 0; fo < 2; fo++) {
                    const int fn = 2 * jg + fo;
                    int sh = (fn & 3) * 8 + t2 * 2;
                    uint32_t w0 = mw0[fn >> 2], w1 = mw1[fn >> 2];
                    float* Cf = C[2*jj + fo];
                    float p0 = ((w0 >> sh) & 1u)       ? 0.f : __expf(Cf[0]);
                    float p1 = ((w0 >> (sh + 1)) & 1u) ? 0.f : __expf(Cf[1]);
                    float p2 = ((w1 >> sh) & 1u)       ? 0.f : __expf(Cf[2]);
                    float p3 = ((w1 >> (sh + 1)) & 1u) ? 0.f : __expf(Cf[3]);
                    rs0 += p0 + p1;
                    rs1 += p2 + p3;
                    __stcs((float2*)(ar0 + fn * 8 + t2 * 2), make_float2(p0, p1));
                    __stcs((float2*)(ar1 + fn * 8 + t2 * 2), make_float2(p2, p3));

                    uint32_t h01 = packbf(p0, p1), h23 = packbf(p2, p3);
                    float f0 = ubf(h01 << 16), f1 = ubf(h01 & 0xFFFF0000u);
                    float f2 = ubf(h23 << 16), f3 = ubf(h23 & 0xFFFF0000u);
                    int o = fo * 2;
                    phi[o] = h01; phi[o + 1] = h23;
                    plo[o] = packbf(p0 - f0, p1 - f1);
                    plo[o + 1] = packbf(p2 - f2, p3 - f3);
                }
#pragma unroll
                for (int dg = 0; dg < 4; dg++) {
                    uint32_t vh[4], vl[4];
                    uint32_t voff = (uint32_t)(jg * 2048 +
                        (((qrow * 128) | (dg * 32) | qbyt) ^ ((qrow & 7) << 4)));
                    ldsm4t(vh, uVH + voff);
                    ldsm4t(vl, uVL + voff);
                    mma16816(OD[2*dg],   phi, vh[0], vh[1]);
                    mma16816(OD[2*dg+1], phi, vh[2], vh[3]);
                    mma16816(OD[2*dg],   phi, vl[0], vl[1]);
                    mma16816(OD[2*dg+1], phi, vl[2], vl[3]);
                    mma16816(OD[2*dg],   plo, vh[0], vh[1]);
                    mma16816(OD[2*dg+1], plo, vh[2], vh[3]);
                }
            }
        }
    }

    // ---- tail: row sums, output, shared inverse for rescale ----
    if (w < NCW) {
        rs0 += __shfl_xor_sync(0xffffffffu, rs0, 1);
        rs0 += __shfl_xor_sync(0xffffffffu, rs0, 2);
        rs1 += __shfl_xor_sync(0xffffffffu, rs1, 1);
        rs1 += __shfl_xor_sync(0xffffffffu, rs1, 2);
        const float inv0 = 1.0f / rs0, inv1 = 1.0f / rs1;
        if (t2 == 0) {
            sInv[w * 16 + g]     = inv0;
            sInv[w * 16 + 8 + g] = inv1;
        }
        float* o0 = out + (size_t)(bq + w * 16 + g) * DD;
        float* o1 = o0 + (size_t)8 * DD;
#pragma unroll
        for (int dn = 0; dn < 8; dn++) {
            *(float2*)(o0 + dn * 8 + t2 * 2) = make_float2(OD[dn][0] * inv0, OD[dn][1] * inv0);
            *(float2*)(o1 + dn * 8 + t2 * 2) = make_float2(OD[dn][2] * inv1, OD[dn][3] * inv1);
        }
    }
    __syncthreads();

    // ---- fused attn normalization: all 12 warps stream the CTA's slice ----
    float4* ap = (float4*)(attn + (size_t)bq * SS);
    for (int u = tid; u < TQ * SS / 4; u += NT) {
        int row = u >> 9;
        float inv = sInv[row];
        float4 a = __ldcs(ap + u);
        a.x *= inv; a.y *= inv; a.z *= inv; a.w *= inv;
        __stcs(ap + u, a);
    }
}

extern "C" void kernel_launch(void* const* d_in, const int* in_sizes, int n_in,
                              void* d_out, int out_size)
{
    const float* q = (const float*)d_in[0];
    const float* k = (const float*)d_in[1];
    const float* v = (const float*)d_in[2];
    const void*  mask = d_in[3];

    float* out  = (float*)d_out;
    float* attn = out + (size_t)BB * SS * DD;   // tuple order: (output, attn)

    cudaFuncSetAttribute(sdpa_ws_kernel,
                         cudaFuncAttributeMaxDynamicSharedMemorySize, SMEM_DYN);

    dim3 grid(SS / TQ, BB);
    sdpa_ws_kernel<<<grid, NT, SMEM_DYN>>>(q, k, v, mask, out, attn);
}

// round 13
// speedup vs baseline: 1.0257x; 1.0257x over previous
#include <cuda_runtime.h>
#include <cuda_bf16.h>
#include <cstdint>

#define BB 16
#define SS 2048
#define DD 64
#define TQ 128
#define NJ 128
#define NT 256
#define NTILES (SS / NJ)

// dynamic smem: Q hi/lo (32KB) + single K/V buffer (64KB)
#define OQH 0
#define OQL 16384
#define OKH 32768
#define OKL 49152
#define OVH 65536
#define OVL 81920
#define SMEM_DYN (98304 + 1024)

#define SWZ(o) ((o) ^ (((o) >> 3) & 0x70u))
#define QSCALE 0.1803368801111249f   // 0.125 * log2(e)

static __device__ __forceinline__ uint32_t packbf(float lo, float hi) {
    uint32_t r;
    asm("cvt.rn.bf16x2.f32 %0, %1, %2;" : "=r"(r) : "f"(hi), "f"(lo));
    return r;
}
static __device__ __forceinline__ float ubf(uint32_t u) { return __uint_as_float(u); }

static __device__ __forceinline__ void ldsm4(uint32_t* r, uint32_t a) {
    asm volatile("ldmatrix.sync.aligned.m8n8.x4.shared.b16 {%0,%1,%2,%3}, [%4];"
        : "=r"(r[0]), "=r"(r[1]), "=r"(r[2]), "=r"(r[3]) : "r"(a));
}
static __device__ __forceinline__ void ldsm4t(uint32_t* r, uint32_t a) {
    asm volatile("ldmatrix.sync.aligned.m8n8.x4.trans.shared.b16 {%0,%1,%2,%3}, [%4];"
        : "=r"(r[0]), "=r"(r[1]), "=r"(r[2]), "=r"(r[3]) : "r"(a));
}
static __device__ __forceinline__ void mma16816(float* c, const uint32_t* a,
                                                uint32_t b0, uint32_t b1) {
    asm volatile("mma.sync.aligned.m16n8k16.row.col.f32.bf16.bf16.f32 "
        "{%0,%1,%2,%3}, {%4,%5,%6,%7}, {%8,%9}, {%0,%1,%2,%3};"
        : "+f"(c[0]), "+f"(c[1]), "+f"(c[2]), "+f"(c[3])
        : "r"(a[0]), "r"(a[1]), "r"(a[2]), "r"(a[3]), "r"(b0), "r"(b1));
}
static __device__ __forceinline__ uint32_t s2u(const void* p) {
    uint32_t a;
    asm("{ .reg .u64 t; cvta.to.shared.u64 t, %1; cvt.u32.u64 %0, t; }" : "=r"(a) : "l"(p));
    return a;
}
static __device__ __forceinline__ uint32_t b2b(uint32_t wv, int sh) {
    uint32_t r = 0;
    r |= ((wv & 0x000000FFu) ? 1u : 0u) << sh;
    r |= ((wv & 0x0000FF00u) ? 1u : 0u) << (sh + 1);
    r |= ((wv & 0x00FF0000u) ? 1u : 0u) << (sh + 2);
    r |= ((wv & 0xFF000000u) ? 1u : 0u) << (sh + 3);
    return r;
}

// stage a [128 x 64] fp32 tile as bf16 hi/lo into SW128 smem
static __device__ __forceinline__ void stage_bf(const float* __restrict__ g,
                                                char* sh, char* sl, float sc, int tid)
{
#pragma unroll
    for (int it = 0; it < 4; it++) {
        int i = it * NT + tid;
        int row = i >> 3, c8 = (i & 7) << 3;
        float4 a = *(const float4*)(g + row * 64 + c8);
        float4 b = *(const float4*)(g + row * 64 + c8 + 4);
        float y[8] = {a.x*sc, a.y*sc, a.z*sc, a.w*sc, b.x*sc, b.y*sc, b.z*sc, b.w*sc};
        uint32_t h[4], l[4];
#pragma unroll
        for (int p = 0; p < 4; p++) {
            h[p] = packbf(y[2*p], y[2*p+1]);
            float f0 = ubf(h[p] << 16), f1 = ubf(h[p] & 0xFFFF0000u);
            l[p] = packbf(y[2*p] - f0, y[2*p+1] - f1);
        }
        uint32_t off = SWZ((uint32_t)(row * 128 + c8 * 2));
        *(uint4*)(sh + off) = make_uint4(h[0], h[1], h[2], h[3]);
        *(uint4*)(sl + off) = make_uint4(l[0], l[1], l[2], l[3]);
    }
}

__global__ __launch_bounds__(NT, 2) void sdpa_mma_kernel(
    const float* __restrict__ q, const float* __restrict__ k,
    const float* __restrict__ v, const void* __restrict__ maskp,
    float* __restrict__ out, float* __restrict__ attn)
{
    const int b   = blockIdx.y;
    const int q0  = blockIdx.x * TQ;
    const int tid = threadIdx.x;
    const int w   = tid >> 5;
    const int lid = tid & 31;
    const int g   = lid >> 2;
    const int t2  = lid & 3;
    const int bq  = b * SS + q0;

    extern __shared__ char dsm_raw[];
    char* dsm = (char*)(((uintptr_t)dsm_raw + 1023) & ~(uintptr_t)1023);
    const uint32_t uQH = s2u(dsm + OQH), uQL = s2u(dsm + OQL);
    const uint32_t uKH = s2u(dsm + OKH), uKL = s2u(dsm + OKL);
    const uint32_t uVH = s2u(dsm + OVH), uVL = s2u(dsm + OVL);

    const float* qb = q + ((size_t)bq) * DD;
    const float* kb = k + (size_t)b * SS * DD;
    const float* vb = v + (size_t)b * SS * DD;
    const unsigned char* m8b  = (const unsigned char*)maskp + (size_t)b * SS * SS;
    const uint32_t*      m32b = (const uint32_t*)maskp + (size_t)b * SS * SS;

    // ---- fused mask-dtype detect over this CTA's own slice ----
    int pF = 0, pB = 0;
    {
        uint4 u = __ldcs((const uint4*)(m32b + (size_t)q0 * SS) + tid);
        uint32_t ws[4] = {u.x, u.y, u.z, u.w};
#pragma unroll
        for (int i = 0; i < 4; i++) {
            if (ws[i] == 0x3F800000u) pF = 1;
            else if (ws[i] > 1u)      pB = 1;
        }
    }

    // Q staged once, pre-scaled by 0.125*log2(e)  (epilogue uses exp2f)
    stage_bf(qb, dsm + OQH, dsm + OQL, QSCALE, tid);

    const int anyF = __syncthreads_or(pF);
    const int anyB = __syncthreads_or(pB);
    const int mk = anyF ? 2 : (anyB ? 0 : 1);   // 0=uint8, 1=int32, 2=float32

    // ldmatrix lane address patterns
    const int krow = (lid & 7) + ((lid >> 4) & 1) * 8;
    const int kbyt = ((lid >> 3) & 1) * 16;
    const int qrow = (lid & 7) + ((lid >> 3) & 1) * 8;
    const int qbyt = ((lid >> 4) & 1) * 16;

    float OD[8][4];
#pragma unroll
    for (int i = 0; i < 8; i++)
#pragma unroll
        for (int jx = 0; jx < 4; jx++) OD[i][jx] = 0.f;

    float rs0 = 0.f, rs1 = 0.f;

    for (int t = 0; t < NTILES; t++) {
        const int j0 = t * NJ;

        if (t > 0) __syncthreads();           // prior tile's GEMM2 done reading
        stage_bf(kb + (size_t)j0 * DD, dsm + OKH, dsm + OKL, 1.0f, tid);
        stage_bf(vb + (size_t)j0 * DD, dsm + OVH, dsm + OVL, 1.0f, tid);
        __syncthreads();

        // ---- hoisted mask loads (uint8 fast path): consumed after GEMM1 half0 ----
        const size_t mrow0 = (size_t)(q0 + w * 16 + g) * SS + j0 + t2 * 32;
        uint4 hm0a, hm0b, hm1a, hm1b;
        uint32_t myb0 = 0, myb1 = 0;
        if (mk == 0) {
            const uint4* p0 = (const uint4*)(m8b + mrow0);
            const uint4* p1 = (const uint4*)(m8b + mrow0 + (size_t)8 * SS);
            hm0a = __ldcs(p0); hm0b = __ldcs(p0 + 1);
            hm1a = __ldcs(p1); hm1b = __ldcs(p1 + 1);
        } else {
            // rare path: pack immediately
            const uint4* p0 = (const uint4*)(m32b + mrow0);
            const uint4* p1 = (const uint4*)(m32b + mrow0 + (size_t)8 * SS);
#pragma unroll
            for (int ii = 0; ii < 8; ii++) {
                uint4 a = __ldcs(p0 + ii);
                myb0 |= (a.x?1u:0u)<<(ii*4)   | (a.y?1u:0u)<<(ii*4+1)
                      | (a.z?1u:0u)<<(ii*4+2) | (a.w?1u:0u)<<(ii*4+3);
                uint4 c = __ldcs(p1 + ii);
                myb1 |= (c.x?1u:0u)<<(ii*4)   | (c.y?1u:0u)<<(ii*4+1)
                      | (c.z?1u:0u)<<(ii*4+2) | (c.w?1u:0u)<<(ii*4+3);
            }
        }

        float* ar0 = attn + ((size_t)(bq + w * 16 + g)) * SS + j0;
        float* ar1 = ar0 + (size_t)8 * SS;
        uint32_t mw0[4], mw1[4];

#pragma unroll
        for (int hf = 0; hf < 2; hf++) {
            float C[8][4];
#pragma unroll
            for (int fn = 0; fn < 8; fn++)
#pragma unroll
                for (int jx = 0; jx < 4; jx++) C[fn][jx] = 0.f;

            // ---- GEMM1: paired K-frag hoist -> 12-MMA bursts over 4 C chains ----
#pragma unroll
            for (int ks = 0; ks < 4; ks++) {
                uint32_t qh[4], ql[4];
                uint32_t qoff = (uint32_t)(w * 2048 +
                    (((qrow * 128) | (ks * 32) | qbyt) ^ ((qrow & 7) << 4)));
                ldsm4(qh, uQH + qoff);
                ldsm4(ql, uQL + qoff);
#pragma unroll
                for (int jp = 0; jp < 2; jp++) {
                    const int jg0 = hf * 4 + 2 * jp;
                    uint32_t kh0[4], kl0[4], kh1[4], kl1[4];
                    uint32_t ko0 = (uint32_t)(jg0 * 2048 +
                        (((krow * 128) | (ks * 32) | kbyt) ^ ((krow & 7) << 4)));
                    uint32_t ko1 = ko0 + 2048;
                    ldsm4(kh0, uKH + ko0);
                    ldsm4(kl0, uKL + ko0);
                    ldsm4(kh1, uKH + ko1);
                    ldsm4(kl1, uKL + ko1);
                    float* c0 = C[4*jp];     float* c1 = C[4*jp+1];
                    float* c2 = C[4*jp+2];   float* c3 = C[4*jp+3];
                    mma16816(c0, qh, kh0[0], kh0[1]);
                    mma16816(c1, qh, kh0[2], kh0[3]);
                    mma16816(c2, qh, kh1[0], kh1[1]);
                    mma16816(c3, qh, kh1[2], kh1[3]);
                    mma16816(c0, qh, kl0[0], kl0[1]);
                    mma16816(c1, qh, kl0[2], kl0[3]);
                    mma16816(c2, qh, kl1[0], kl1[1]);
                    mma16816(c3, qh, kl1[2], kl1[3]);
                    mma16816(c0, ql, kh0[0], kh0[1]);
                    mma16816(c1, ql, kh0[2], kh0[3]);
                    mma16816(c2, ql, kh1[0], kh1[1]);
                    mma16816(c3, ql, kh1[2], kh1[3]);
                }
            }

            if (hf == 0) {
                if (mk == 0) {
                    myb0 = b2b(hm0a.x,0)|b2b(hm0a.y,4)|b2b(hm0a.z,8)|b2b(hm0a.w,12)
                         | b2b(hm0b.x,16)|b2b(hm0b.y,20)|b2b(hm0b.z,24)|b2b(hm0b.w,28);
                    myb1 = b2b(hm1a.x,0)|b2b(hm1a.y,4)|b2b(hm1a.z,8)|b2b(hm1a.w,12)
                         | b2b(hm1b.x,16)|b2b(hm1b.y,20)|b2b(hm1b.z,24)|b2b(hm1b.w,28);
                }
#pragma unroll
                for (int i = 0; i < 4; i++) {
                    mw0[i] = __shfl_sync(0xffffffffu, myb0, (lid & ~3) | i);
                    mw1[i] = __shfl_sync(0xffffffffu, myb1, (lid & ~3) | i);
                }
            }

            // ---- per-slab epilogue + GEMM2 (paired V-frag hoist) ----
#pragma unroll
            for (int jj = 0; jj < 4; jj++) {
                const int jg = hf * 4 + jj;
                uint32_t phi[4], plo[4];
#pragma unroll
                for (int fo = 0; fo < 2; fo++) {
                    const int fn = 2 * jg + fo;
                    int sh = (fn & 3) * 8 + t2 * 2;
                    uint32_t w0 = mw0[fn >> 2], w1 = mw1[fn >> 2];
                    float* Cf = C[2*jj + fo];
                    float p0 = ((w0 >> sh) & 1u)       ? 0.f : exp2f(Cf[0]);
                    float p1 = ((w0 >> (sh + 1)) & 1u) ? 0.f : exp2f(Cf[1]);
                    float p2 = ((w1 >> sh) & 1u)       ? 0.f : exp2f(Cf[2]);
                    float p3 = ((w1 >> (sh + 1)) & 1u) ? 0.f : exp2f(Cf[3]);
                    rs0 += p0 + p1;
                    rs1 += p2 + p3;
                    __stcs((float2*)(ar0 + fn * 8 + t2 * 2), make_float2(p0, p1));
                    __stcs((float2*)(ar1 + fn * 8 + t2 * 2), make_float2(p2, p3));

                    uint32_t h01 = packbf(p0, p1), h23 = packbf(p2, p3);
                    float f0 = ubf(h01 << 16), f1 = ubf(h01 & 0xFFFF0000u);
                    float f2 = ubf(h23 << 16), f3 = ubf(h23 & 0xFFFF0000u);
                    int o = fo * 2;
                    phi[o] = h01; phi[o + 1] = h23;
                    plo[o] = packbf(p0 - f0, p1 - f1);
                    plo[o + 1] = packbf(p2 - f2, p3 - f3);
                }
#pragma unroll
                for (int dp = 0; dp < 2; dp++) {
                    uint32_t vh0[4], vl0[4], vh1[4], vl1[4];
                    uint32_t vo0 = (uint32_t)(jg * 2048 +
                        (((qrow * 128) | (dp * 64) | qbyt) ^ ((qrow & 7) << 4)));
                    uint32_t vo1 = (uint32_t)(jg * 2048 +
                        (((qrow * 128) | (dp * 64 + 32) | qbyt) ^ ((qrow & 7) << 4)));
                    ldsm4t(vh0, uVH + vo0);
                    ldsm4t(vl0, uVL + vo0);
                    ldsm4t(vh1, uVH + vo1);
                    ldsm4t(vl1, uVL + vo1);
                    float* d0 = OD[4*dp];     float* d1 = OD[4*dp+1];
                    float* d2 = OD[4*dp+2];   float* d3 = OD[4*dp+3];
                    mma16816(d0, phi, vh0[0], vh0[1]);
                    mma16816(d1, phi, vh0[2], vh0[3]);
                    mma16816(d2, phi, vh1[0], vh1[1]);
                    mma16816(d3, phi, vh1[2], vh1[3]);
                    mma16816(d0, phi, vl0[0], vl0[1]);
                    mma16816(d1, phi, vl0[2], vl0[3]);
                    mma16816(d2, phi, vl1[0], vl1[1]);
                    mma16816(d3, phi, vl1[2], vl1[3]);
                    mma16816(d0, plo, vh0[0], vh0[1]);
                    mma16816(d1, plo, vh0[2], vh0[3]);
                    mma16816(d2, plo, vh1[0], vh1[1]);
                    mma16816(d3, plo, vh1[2], vh1[3]);
                }
            }
        }
    }

    // ---- row sums: quad-reduce (lanes in a quad share rows) ----
    rs0 += __shfl_xor_sync(0xffffffffu, rs0, 1);
    rs0 += __shfl_xor_sync(0xffffffffu, rs0, 2);
    rs1 += __shfl_xor_sync(0xffffffffu, rs1, 1);
    rs1 += __shfl_xor_sync(0xffffffffu, rs1, 2);
    const float inv0 = 1.0f / rs0, inv1 = 1.0f / rs1;

    // ---- output: scale PV accumulators ----
    float* o0 = out + (size_t)(bq + w * 16 + g) * DD;
    float* o1 = o0 + (size_t)8 * DD;
#pragma unroll
    for (int dn = 0; dn < 8; dn++) {
        *(float2*)(o0 + dn * 8 + t2 * 2) = make_float2(OD[dn][0] * inv0, OD[dn][1] * inv0);
        *(float2*)(o1 + dn * 8 + t2 * 2) = make_float2(OD[dn][2] * inv1, OD[dn][3] * inv1);
    }

    // ---- fused attn normalization: each quad rescales its own two rows ----
    float4* r0p = (float4*)(attn + (size_t)(bq + w * 16 + g) * SS);
    float4* r1p = (float4*)(attn + (size_t)(bq + w * 16 + 8 + g) * SS);
#pragma unroll 4
    for (int j4 = t2; j4 < SS / 4; j4 += 4) {
        float4 a = __ldcs(r0p + j4);
        a.x *= inv0; a.y *= inv0; a.z *= inv0; a.w *= inv0;
        __stcs(r0p + j4, a);
        float4 c = __ldcs(r1p + j4);
        c.x *= inv1; c.y *= inv1; c.z *= inv1; c.w *= inv1;
        __stcs(r1p + j4, c);
    }
}

extern "C" void kernel_launch(void* const* d_in, const int* in_sizes, int n_in,
                              void* d_out, int out_size)
{
    const float* q = (const float*)d_in[0];
    const float* k = (const float*)d_in[1];
    const float* v = (const float*)d_in[2];
    const void*  mask = d_in[3];

    float* out  = (float*)d_out;
    float* attn = out + (size_t)BB * SS * DD;   // tuple order: (output, attn)

    cudaFuncSetAttribute(sdpa_mma_kernel,
                         cudaFuncAttributeMaxDynamicSharedMemorySize, SMEM_DYN);

    dim3 grid(SS / TQ, BB);
    sdpa_mma_kernel<<<grid, NT, SMEM_DYN>>>(q, k, v, mask, out, attn);
}

// round 14
// speedup vs baseline: 1.2141x; 1.1837x over previous
#include <cuda_runtime.h>
#include <cuda_bf16.h>
#include <cstdint>

#define BB 16
#define SS 2048
#define DD 64
#define TQ 64
#define NJ 64
#define NT 128
#define NTILES (SS / NJ)

// dynamic smem: Q hi/lo (16KB) + K hi/lo (16KB) + V hi/lo (16KB) + inv
#define OQH 0
#define OQL 8192
#define OKH 16384
#define OKL 24576
#define OVH 32768
#define OVL 40960
#define OINV 49152
#define SMEM_DYN (49152 + 256 + 1024)

#define SWZ(o) ((o) ^ (((o) >> 3) & 0x70u))
#define QSCALE 0.1803368801111249f   // 0.125 * log2(e)

static __device__ __forceinline__ uint32_t packbf(float lo, float hi) {
    uint32_t r;
    asm("cvt.rn.bf16x2.f32 %0, %1, %2;" : "=r"(r) : "f"(hi), "f"(lo));
    return r;
}
static __device__ __forceinline__ float ubf(uint32_t u) { return __uint_as_float(u); }

static __device__ __forceinline__ void ldsm4(uint32_t* r, uint32_t a) {
    asm volatile("ldmatrix.sync.aligned.m8n8.x4.shared.b16 {%0,%1,%2,%3}, [%4];"
        : "=r"(r[0]), "=r"(r[1]), "=r"(r[2]), "=r"(r[3]) : "r"(a));
}
static __device__ __forceinline__ void ldsm4t(uint32_t* r, uint32_t a) {
    asm volatile("ldmatrix.sync.aligned.m8n8.x4.trans.shared.b16 {%0,%1,%2,%3}, [%4];"
        : "=r"(r[0]), "=r"(r[1]), "=r"(r[2]), "=r"(r[3]) : "r"(a));
}
static __device__ __forceinline__ void mma16816(float* c, const uint32_t* a,
                                                uint32_t b0, uint32_t b1) {
    asm volatile("mma.sync.aligned.m16n8k16.row.col.f32.bf16.bf16.f32 "
        "{%0,%1,%2,%3}, {%4,%5,%6,%7}, {%8,%9}, {%0,%1,%2,%3};"
        : "+f"(c[0]), "+f"(c[1]), "+f"(c[2]), "+f"(c[3])
        : "r"(a[0]), "r"(a[1]), "r"(a[2]), "r"(a[3]), "r"(b0), "r"(b1));
}
static __device__ __forceinline__ uint32_t s2u(const void* p) {
    uint32_t a;
    asm("{ .reg .u64 t; cvta.to.shared.u64 t, %1; cvt.u32.u64 %0, t; }" : "=r"(a) : "l"(p));
    return a;
}
static __device__ __forceinline__ uint32_t b2b(uint32_t wv, int sh) {
    uint32_t r = 0;
    r |= ((wv & 0x000000FFu) ? 1u : 0u) << sh;
    r |= ((wv & 0x0000FF00u) ? 1u : 0u) << (sh + 1);
    r |= ((wv & 0x00FF0000u) ? 1u : 0u) << (sh + 2);
    r |= ((wv & 0xFF000000u) ? 1u : 0u) << (sh + 3);
    return r;
}

// stage a [64 x 64] fp32 tile as bf16 hi/lo into SW128 smem (128 threads)
static __device__ __forceinline__ void stage_bf(const float* __restrict__ g,
                                                char* sh, char* sl, float sc, int tid)
{
#pragma unroll
    for (int it = 0; it < 4; it++) {
        int i = it * NT + tid;             // 0..511  (64 rows x 8 col-groups)
        int row = i >> 3, c8 = (i & 7) << 3;
        float4 a = *(const float4*)(g + row * 64 + c8);
        float4 b = *(const float4*)(g + row * 64 + c8 + 4);
        float y[8] = {a.x*sc, a.y*sc, a.z*sc, a.w*sc, b.x*sc, b.y*sc, b.z*sc, b.w*sc};
        uint32_t h[4], l[4];
#pragma unroll
        for (int p = 0; p < 4; p++) {
            h[p] = packbf(y[2*p], y[2*p+1]);
            float f0 = ubf(h[p] << 16), f1 = ubf(h[p] & 0xFFFF0000u);
            l[p] = packbf(y[2*p] - f0, y[2*p+1] - f1);
        }
        uint32_t off = SWZ((uint32_t)(row * 128 + c8 * 2));
        *(uint4*)(sh + off) = make_uint4(h[0], h[1], h[2], h[3]);
        *(uint4*)(sl + off) = make_uint4(l[0], l[1], l[2], l[3]);
    }
}

__global__ __launch_bounds__(NT, 4) void sdpa_mma_kernel(
    const float* __restrict__ q, const float* __restrict__ k,
    const float* __restrict__ v, const void* __restrict__ maskp,
    float* __restrict__ out, float* __restrict__ attn)
{
    const int b   = blockIdx.y;
    const int q0  = blockIdx.x * TQ;
    const int tid = threadIdx.x;
    const int w   = tid >> 5;          // 0..3, warp owns rows w*16..w*16+15
    const int lid = tid & 31;
    const int g   = lid >> 2;
    const int t2  = lid & 3;
    const int bq  = b * SS + q0;

    extern __shared__ char dsm_raw[];
    char* dsm = (char*)(((uintptr_t)dsm_raw + 1023) & ~(uintptr_t)1023);
    float* sInv = (float*)(dsm + OINV);
    const uint32_t uQH = s2u(dsm + OQH), uQL = s2u(dsm + OQL);
    const uint32_t uKH = s2u(dsm + OKH), uKL = s2u(dsm + OKL);
    const uint32_t uVH = s2u(dsm + OVH), uVL = s2u(dsm + OVL);

    const float* qb = q + ((size_t)bq) * DD;
    const float* kb = k + (size_t)b * SS * DD;
    const float* vb = v + (size_t)b * SS * DD;
    const unsigned char* m8b  = (const unsigned char*)maskp + (size_t)b * SS * SS;
    const uint32_t*      m32b = (const uint32_t*)maskp + (size_t)b * SS * SS;

    // ---- fused mask-dtype detect over this CTA's own slice (512 words) ----
    int pF = 0, pB = 0;
    {
        uint4 u = __ldcs((const uint4*)(m32b + (size_t)q0 * SS) + tid);
        uint32_t ws[4] = {u.x, u.y, u.z, u.w};
#pragma unroll
        for (int i = 0; i < 4; i++) {
            if (ws[i] == 0x3F800000u) pF = 1;
            else if (ws[i] > 1u)      pB = 1;
        }
    }

    // Q staged once, pre-scaled by 0.125*log2(e) (epilogue uses exp2f)
    stage_bf(qb, dsm + OQH, dsm + OQL, QSCALE, tid);

    const int anyF = __syncthreads_or(pF);
    const int anyB = __syncthreads_or(pB);
    const int mk = anyF ? 2 : (anyB ? 0 : 1);   // 0=uint8, 1=int32, 2=float32

    // ldmatrix lane address patterns
    const int krow = (lid & 7) + ((lid >> 4) & 1) * 8;
    const int kbyt = ((lid >> 3) & 1) * 16;
    const int qrow = (lid & 7) + ((lid >> 3) & 1) * 8;
    const int qbyt = ((lid >> 4) & 1) * 16;

    // mask lane roles: rsel = row (g or g+8), half = j-half (32 j each)
    const int rsel = t2 >> 1;
    const int half = t2 & 1;
    const int qb4  = g * 4;

    float OD[8][4];
#pragma unroll
    for (int i = 0; i < 8; i++)
#pragma unroll
        for (int jx = 0; jx < 4; jx++) OD[i][jx] = 0.f;

    float rs0 = 0.f, rs1 = 0.f;

    for (int t = 0; t < NTILES; t++) {
        const int j0 = t * NJ;

        if (t > 0) __syncthreads();
        stage_bf(kb + (size_t)j0 * DD, dsm + OKH, dsm + OKL, 1.0f, tid);
        stage_bf(vb + (size_t)j0 * DD, dsm + OVH, dsm + OVL, 1.0f, tid);
        __syncthreads();

        // ---- hoisted mask loads: lane covers (row g+rsel*8, j-half) = 32 bits ----
        const size_t mrow = (size_t)(q0 + w * 16 + g + rsel * 8) * SS + j0 + half * 32;
        uint4 hma, hmb;
        uint32_t myb = 0;
        if (mk == 0) {
            const uint4* p0 = (const uint4*)(m8b + mrow);
            hma = __ldcs(p0); hmb = __ldcs(p0 + 1);
        } else {
            const uint4* p0 = (const uint4*)(m32b + mrow);
#pragma unroll
            for (int ii = 0; ii < 8; ii++) {
                uint4 a = __ldcs(p0 + ii);
                myb |= (a.x?1u:0u)<<(ii*4)   | (a.y?1u:0u)<<(ii*4+1)
                     | (a.z?1u:0u)<<(ii*4+2) | (a.w?1u:0u)<<(ii*4+3);
            }
        }

        // ---- GEMM1: C[8][4] = Q(16q) x K^T(64j), 3-term bf16 split ----
        float C[8][4];
#pragma unroll
        for (int fn = 0; fn < 8; fn++)
#pragma unroll
            for (int jx = 0; jx < 4; jx++) C[fn][jx] = 0.f;

#pragma unroll
        for (int ks = 0; ks < 4; ks++) {
            uint32_t qh[4], ql[4];
            uint32_t qoff = (uint32_t)(w * 2048 +
                (((qrow * 128) | (ks * 32) | qbyt) ^ ((qrow & 7) << 4)));
            ldsm4(qh, uQH + qoff);
            ldsm4(ql, uQL + qoff);
#pragma unroll
            for (int jg = 0; jg < 4; jg++) {
                uint32_t kh[4], kl[4];
                uint32_t koff = (uint32_t)(jg * 2048 +
                    (((krow * 128) | (ks * 32) | kbyt) ^ ((krow & 7) << 4)));
                ldsm4(kh, uKH + koff);
                ldsm4(kl, uKL + koff);
                mma16816(C[2*jg],   qh, kh[0], kh[1]);
                mma16816(C[2*jg+1], qh, kh[2], kh[3]);
                mma16816(C[2*jg],   qh, kl[0], kl[1]);
                mma16816(C[2*jg+1], qh, kl[2], kl[3]);
                mma16816(C[2*jg],   ql, kh[0], kh[1]);
                mma16816(C[2*jg+1], ql, kh[2], kh[3]);
            }
        }

        // pack + distribute mask bits (LDG latency hidden behind GEMM1)
        if (mk == 0) {
            myb = b2b(hma.x,0)|b2b(hma.y,4)|b2b(hma.z,8)|b2b(hma.w,12)
                | b2b(hmb.x,16)|b2b(hmb.y,20)|b2b(hmb.z,24)|b2b(hmb.w,28);
        }
        uint32_t mw0[2], mw1[2];
#pragma unroll
        for (int i = 0; i < 2; i++) {
            mw0[i] = __shfl_sync(0xffffffffu, myb, qb4 + i);        // row g, half i
            mw1[i] = __shfl_sync(0xffffffffu, myb, qb4 + 2 + i);    // row g+8, half i
        }

        float* ar0 = attn + ((size_t)(bq + w * 16 + g)) * SS + j0;
        float* ar1 = ar0 + (size_t)8 * SS;

        // ---- per-slab epilogue + GEMM2 ----
#pragma unroll
        for (int jj = 0; jj < 4; jj++) {
            uint32_t phi[4], plo[4];
#pragma unroll
            for (int fo = 0; fo < 2; fo++) {
                const int fn = 2 * jj + fo;
                const int wsel = jj >> 1;
                const int sh = (jj & 1) * 16 + fo * 8 + t2 * 2;
                uint32_t w0 = mw0[wsel], w1 = mw1[wsel];
                float* Cf = C[fn];
                float p0 = ((w0 >> sh) & 1u)       ? 0.f : exp2f(Cf[0]);
                float p1 = ((w0 >> (sh + 1)) & 1u) ? 0.f : exp2f(Cf[1]);
                float p2 = ((w1 >> sh) & 1u)       ? 0.f : exp2f(Cf[2]);
                float p3 = ((w1 >> (sh + 1)) & 1u) ? 0.f : exp2f(Cf[3]);
                rs0 += p0 + p1;
                rs1 += p2 + p3;
                __stcs((float2*)(ar0 + fn * 8 + t2 * 2), make_float2(p0, p1));
                __stcs((float2*)(ar1 + fn * 8 + t2 * 2), make_float2(p2, p3));

                uint32_t h01 = packbf(p0, p1), h23 = packbf(p2, p3);
                float f0 = ubf(h01 << 16), f1 = ubf(h01 & 0xFFFF0000u);
                float f2 = ubf(h23 << 16), f3 = ubf(h23 & 0xFFFF0000u);
                int o = fo * 2;
                phi[o] = h01; phi[o + 1] = h23;
                plo[o] = packbf(p0 - f0, p1 - f1);
                plo[o + 1] = packbf(p2 - f2, p3 - f3);
            }
#pragma unroll
            for (int dg = 0; dg < 4; dg++) {
                uint32_t vh[4], vl[4];
                uint32_t voff = (uint32_t)(jj * 2048 +
                    (((qrow * 128) | (dg * 32) | qbyt) ^ ((qrow & 7) << 4)));
                ldsm4t(vh, uVH + voff);
                ldsm4t(vl, uVL + voff);
                mma16816(OD[2*dg],   phi, vh[0], vh[1]);
                mma16816(OD[2*dg+1], phi, vh[2], vh[3]);
                mma16816(OD[2*dg],   phi, vl[0], vl[1]);
                mma16816(OD[2*dg+1], phi, vl[2], vl[3]);
                mma16816(OD[2*dg],   plo, vh[0], vh[1]);
                mma16816(OD[2*dg+1], plo, vh[2], vh[3]);
            }
        }
    }

    // ---- row sums: quad-reduce (lanes in a quad share rows) ----
    rs0 += __shfl_xor_sync(0xffffffffu, rs0, 1);
    rs0 += __shfl_xor_sync(0xffffffffu, rs0, 2);
    rs1 += __shfl_xor_sync(0xffffffffu, rs1, 1);
    rs1 += __shfl_xor_sync(0xffffffffu, rs1, 2);
    const float inv0 = 1.0f / rs0, inv1 = 1.0f / rs1;
    if (t2 == 0) {
        sInv[w * 16 + g]     = inv0;
        sInv[w * 16 + 8 + g] = inv1;
    }

    // ---- output: scale PV accumulators ----
    float* o0 = out + (size_t)(bq + w * 16 + g) * DD;
    float* o1 = o0 + (size_t)8 * DD;
#pragma unroll
    for (int dn = 0; dn < 8; dn++) {
        *(float2*)(o0 + dn * 8 + t2 * 2) = make_float2(OD[dn][0] * inv0, OD[dn][1] * inv0);
        *(float2*)(o1 + dn * 8 + t2 * 2) = make_float2(OD[dn][2] * inv1, OD[dn][3] * inv1);
    }
    __syncthreads();

    // ---- fused attn normalization: whole CTA streams its 64-row slice ----
    float4* ap = (float4*)(attn + (size_t)bq * SS);
    for (int u = tid; u < TQ * SS / 4; u += NT) {
        int row = u >> 9;
        float inv = sInv[row];
        float4 a = __ldcs(ap + u);
        a.x *= inv; a.y *= inv; a.z *= inv; a.w *= inv;
        __stcs(ap + u, a);
    }
}

extern "C" void kernel_launch(void* const* d_in, const int* in_sizes, int n_in,
                              void* d_out, int out_size)
{
    const float* q = (const float*)d_in[0];
    const float* k = (const float*)d_in[1];
    const float* v = (const float*)d_in[2];
    const void*  mask = d_in[3];

    float* out  = (float*)d_out;
    float* attn = out + (size_t)BB * SS * DD;   // tuple order: (output, attn)

    cudaFuncSetAttribute(sdpa_mma_kernel,
                         cudaFuncAttributeMaxDynamicSharedMemorySize, SMEM_DYN);

    dim3 grid(SS / TQ, BB);
    sdpa_mma_kernel<<<grid, NT, SMEM_DYN>>>(q, k, v, mask, out, attn);
}